// round 7
// baseline (speedup 1.0000x reference)
#include <cuda_runtime.h>
#include <cstdint>
#include <math.h>

// ---------------- problem constants ----------------
#define DIMN 768
#define NL   13
#define NH   12
#define HD   64
#define VOCAB 50257
#define SEQ  512
#define BATCH 4
#define HID  3072
#define BT   (BATCH*SEQ)      // 2048
#define QKVW (3*DIMN)         // 2304

// ---------------- gemm config ----------------
// Tile 128x128, K-chunk 64 int8. 8 warps (2m x 4n), warp tile 64x32.
// SMEM plane: 128 rows x 80 bytes (64 data + 16 pad). 3 stages.
#define PLANE_B 10240
#define ROW_B   80
#define SM_GHOST (3 * 3 * PLANE_B)   // 92160
#define SM_DENSE (3 * 4 * PLANE_B)   // 122880

// ---------------- scratch (device globals; no allocation) ----------------
__device__ float g_x  [(size_t)BT*DIMN];
__device__ float g_qkv[(size_t)BT*QKVW];
__device__ float g_att[(size_t)BT*DIMN];
__device__ float g_mlp[(size_t)BT*HID];
__device__ char  g_qa_h[(size_t)BT*HID];
__device__ char  g_qa_l[(size_t)BT*HID];
__device__ float g_sa [BT];
__device__ float g_s0 [BT];
// pre-converted weights
__device__ char  wq_h[(size_t)NL*QKVW*DIMN];
__device__ char  wq_l[(size_t)NL*QKVW*DIMN];
__device__ float wq_s[(size_t)NL*QKVW];
__device__ char  wp_h[(size_t)NL*DIMN*DIMN];
__device__ char  wp_l[(size_t)NL*DIMN*DIMN];
__device__ float wp_s[(size_t)NL*DIMN];
__device__ unsigned char w1_u[(size_t)NL*HID*DIMN];
__device__ unsigned char w2_u[(size_t)NL*DIMN*HID];
__device__ unsigned char wh_u[(size_t)VOCAB*DIMN];

// ---------------- helpers ----------------
__device__ __forceinline__ float gelu_tanh(float x) {
    float x3 = x * x * x;
    return 0.5f * x * (1.0f + tanhf(0.7978845608028654f * (x + 0.044715f * x3)));
}
__device__ __forceinline__ uint32_t smem_u32(const void* p) {
    uint32_t a;
    asm("{ .reg .u64 t; cvta.to.shared.u64 t, %1; cvt.u32.u64 %0, t; }" : "=r"(a) : "l"(p));
    return a;
}
__device__ __forceinline__ void cp16(uint32_t dst, const void* src) {
    asm volatile("cp.async.cg.shared.global [%0], [%1], 16;" :: "r"(dst), "l"(src));
}
#define CP_COMMIT() asm volatile("cp.async.commit_group;" ::: "memory")
#define CP_WAIT1()  asm volatile("cp.async.wait_group 1;" ::: "memory")
#define CP_WAIT0()  asm volatile("cp.async.wait_group 0;" ::: "memory")

#define LDSM4(r0, r1, r2, r3, addr)                                           \
    asm volatile("ldmatrix.sync.aligned.m8n8.x4.shared.b16 {%0,%1,%2,%3}, [%4];" \
        : "=r"(r0), "=r"(r1), "=r"(r2), "=r"(r3) : "r"(addr))

// int8 IMMA: A s8, B u8 (ghost)
#define IMMA_SU(c, a0,a1,a2,a3, b0,b1)                                        \
    asm volatile(                                                             \
        "mma.sync.aligned.m16n8k32.row.col.s32.s8.u8.s32 "                    \
        "{%0,%1,%2,%3}, {%4,%5,%6,%7}, {%8,%9}, {%0,%1,%2,%3};"               \
        : "+r"((c)[0]), "+r"((c)[1]), "+r"((c)[2]), "+r"((c)[3])              \
        : "r"(a0), "r"(a1), "r"(a2), "r"(a3), "r"(b0), "r"(b1))
// int8 IMMA: A s8, B s8 (dense)
#define IMMA_SS(c, a0,a1,a2,a3, b0,b1)                                        \
    asm volatile(                                                             \
        "mma.sync.aligned.m16n8k32.row.col.s32.s8.s8.s32 "                    \
        "{%0,%1,%2,%3}, {%4,%5,%6,%7}, {%8,%9}, {%0,%1,%2,%3};"               \
        : "+r"((c)[0]), "+r"((c)[1]), "+r"((c)[2]), "+r"((c)[3])              \
        : "r"(a0), "r"(a1), "r"(a2), "r"(a3), "r"(b0), "r"(b1))

// quantize: v = s*(h + l/254), s = rowmax/127
__device__ __forceinline__ void quant2(float v, float inv_s, char& h, char& l) {
    float q = v * inv_s;
    float qr = fminf(fmaxf(rintf(q), -127.f), 127.f);
    float r = fminf(fmaxf(rintf((q - qr) * 254.f), -127.f), 127.f);
    h = (char)(int)qr;
    l = (char)(int)r;
}

// ---------------- weight conversion ----------------
__global__ void conv_w_int8(const float* __restrict__ w, char* __restrict__ qh,
                            char* __restrict__ ql, float* __restrict__ sw, int K) {
    int r = blockIdx.x, tid = threadIdx.x;
    const float* wr = w + (size_t)r * K;
    __shared__ float red[256];
    float mx = 0.f;
    for (int k = tid; k < K; k += 256) mx = fmaxf(mx, fabsf(wr[k]));
    red[tid] = mx; __syncthreads();
    for (int s = 128; s > 0; s >>= 1) { if (tid < s) red[tid] = fmaxf(red[tid], red[tid + s]); __syncthreads(); }
    float M = red[0];
    float s_ = (M > 0.f) ? M / 127.f : 1.f;
    float inv = (M > 0.f) ? 127.f / M : 0.f;
    if (tid == 0) sw[r] = s_;
    for (int k = tid; k < K; k += 256) {
        char h, l; quant2(wr[k], inv, h, l);
        qh[(size_t)r * K + k] = h; ql[(size_t)r * K + k] = l;
    }
}

__global__ void conv_idx_u8(const int* __restrict__ idx, unsigned char* __restrict__ o, size_t n) {
    size_t i = ((size_t)blockIdx.x * blockDim.x + threadIdx.x) * 16;
    if (i >= n) return;
    unsigned char b[16];
    #pragma unroll
    for (int q = 0; q < 4; q++) {
        int4 a = *(const int4*)(idx + i + q * 4);
        b[q*4+0] = (unsigned char)a.x; b[q*4+1] = (unsigned char)a.y;
        b[q*4+2] = (unsigned char)a.z; b[q*4+3] = (unsigned char)a.w;
    }
    *(uint4*)(o + i) = *(uint4*)b;
}

// ---------------- embedding ----------------
__global__ void embed_kernel(const int* __restrict__ idx, const float* __restrict__ tok,
                             const float* __restrict__ pos, float* __restrict__ x) {
    int r = blockIdx.x;
    int t = r % SEQ;
    int token = idx[r];
    const float* tr = tok + (size_t)token * DIMN;
    const float* pr = pos + (size_t)t * DIMN;
    float* xr = x + (size_t)r * DIMN;
    for (int d = threadIdx.x; d < DIMN; d += blockDim.x)
        xr[d] = tr[d] + pr[d];
}

// ---------------- layernorm -> int8 planes + scale + rowsum ----------------
__global__ void ln_quant(const float* __restrict__ x, const float* __restrict__ g,
                         const float* __restrict__ b,
                         char* __restrict__ qh, char* __restrict__ ql,
                         float* __restrict__ sa, float* __restrict__ s0) {
    int r = blockIdx.x, tid = threadIdx.x;
    const float* xr = x + (size_t)r * DIMN;
    __shared__ float red[256];

    float v0 = xr[tid], v1 = xr[tid + 256], v2 = xr[tid + 512];
    red[tid] = v0 + v1 + v2;
    __syncthreads();
    for (int s = 128; s > 0; s >>= 1) { if (tid < s) red[tid] += red[tid + s]; __syncthreads(); }
    float mean = red[0] * (1.0f / DIMN);
    __syncthreads();
    float d0 = v0 - mean, d1 = v1 - mean, d2 = v2 - mean;
    red[tid] = d0 * d0 + d1 * d1 + d2 * d2;
    __syncthreads();
    for (int s = 128; s > 0; s >>= 1) { if (tid < s) red[tid] += red[tid + s]; __syncthreads(); }
    float inv = rsqrtf(red[0] * (1.0f / DIMN) + 1e-5f);
    float o0 = d0 * inv * g[tid]       + b[tid];
    float o1 = d1 * inv * g[tid + 256] + b[tid + 256];
    float o2 = d2 * inv * g[tid + 512] + b[tid + 512];
    __syncthreads();
    red[tid] = o0 + o1 + o2;
    __syncthreads();
    for (int s = 128; s > 0; s >>= 1) { if (tid < s) red[tid] += red[tid + s]; __syncthreads(); }
    float S = red[0];
    __syncthreads();
    red[tid] = fmaxf(fmaxf(fabsf(o0), fabsf(o1)), fabsf(o2));
    __syncthreads();
    for (int s = 128; s > 0; s >>= 1) { if (tid < s) red[tid] = fmaxf(red[tid], red[tid + s]); __syncthreads(); }
    float M = red[0];
    float sc = (M > 0.f) ? M / 127.f : 1.f;
    float iq = (M > 0.f) ? 127.f / M : 0.f;
    if (tid == 0) { sa[r] = sc; s0[r] = S; }
    size_t base = (size_t)r * DIMN;
    char h, l;
    quant2(o0, iq, h, l); qh[base + tid]       = h; ql[base + tid]       = l;
    quant2(o1, iq, h, l); qh[base + tid + 256] = h; ql[base + tid + 256] = l;
    quant2(o2, iq, h, l); qh[base + tid + 512] = h; ql[base + tid + 512] = l;
}

// ---------------- generic row quantizer (fp32 rows -> planes + scale + sum) ----------------
__global__ void quant_rows(const float* __restrict__ xin,
                           char* __restrict__ qh, char* __restrict__ ql,
                           float* __restrict__ sa, float* __restrict__ s0, int K) {
    int r = blockIdx.x, tid = threadIdx.x;
    const float* xr = xin + (size_t)r * K;
    __shared__ float red[256];
    float mx = 0.f, sm = 0.f;
    for (int k = tid; k < K; k += 256) {
        float v = xr[k];
        mx = fmaxf(mx, fabsf(v)); sm += v;
    }
    red[tid] = sm; __syncthreads();
    for (int s = 128; s > 0; s >>= 1) { if (tid < s) red[tid] += red[tid + s]; __syncthreads(); }
    float S = red[0];
    __syncthreads();
    red[tid] = mx; __syncthreads();
    for (int s = 128; s > 0; s >>= 1) { if (tid < s) red[tid] = fmaxf(red[tid], red[tid + s]); __syncthreads(); }
    float M = red[0];
    float sc = (M > 0.f) ? M / 127.f : 1.f;
    float iq = (M > 0.f) ? 127.f / M : 0.f;
    if (tid == 0) { sa[r] = sc; s0[r] = S; }
    for (int k = tid; k < K; k += 256) {
        char h, l; quant2(xr[k], iq, h, l);
        qh[(size_t)r * K + k] = h; ql[(size_t)r * K + k] = l;
    }
}

// ---------------- attention (fp32 in/out) ----------------
__global__ void attn_kernel(const float* __restrict__ qkv, float* __restrict__ out) {
    int q = blockIdx.x, h = blockIdx.y, b = blockIdx.z;
    int tid = threadIdx.x;
    __shared__ float qs[HD];
    __shared__ float sc[SEQ];
    __shared__ float red[128];

    const float* qrow = qkv + ((size_t)(b * SEQ + q)) * QKVW + h * HD;
    if (tid < HD) qs[tid] = qrow[tid];
    __syncthreads();

    int n = q + 1;
    for (int k = tid; k < n; k += 128) {
        const float* krow = qkv + ((size_t)(b * SEQ + k)) * QKVW + DIMN + h * HD;
        float s = 0.f;
        #pragma unroll
        for (int d = 0; d < HD; d++) s += qs[d] * krow[d];
        sc[k] = s * 0.125f;
    }
    __syncthreads();

    float m = -1e30f;
    for (int k = tid; k < n; k += 128) m = fmaxf(m, sc[k]);
    red[tid] = m; __syncthreads();
    for (int s = 64; s > 0; s >>= 1) { if (tid < s) red[tid] = fmaxf(red[tid], red[tid + s]); __syncthreads(); }
    m = red[0];
    __syncthreads();

    float ssum = 0.f;
    for (int k = tid; k < n; k += 128) { float e = expf(sc[k] - m); sc[k] = e; ssum += e; }
    red[tid] = ssum; __syncthreads();
    for (int s = 64; s > 0; s >>= 1) { if (tid < s) red[tid] += red[tid + s]; __syncthreads(); }
    float inv = 1.0f / red[0];
    __syncthreads();

    int d = tid & 63, half_ = tid >> 6;
    float acc = 0.f;
    for (int k = half_; k < n; k += 2) {
        const float* vrow = qkv + ((size_t)(b * SEQ + k)) * QKVW + 2 * DIMN + h * HD;
        acc += sc[k] * vrow[d];
    }
    red[tid] = acc; __syncthreads();
    if (tid < HD)
        out[((size_t)(b * SEQ + q)) * DIMN + h * HD + tid] = (red[tid] + red[tid + 64]) * inv;
}

// ---------------- int8 IMMA GEMM ----------------
// C[M,N] = A[M,K] @ B[N,K]^T with per-row quantized operands.
// GHOST: B = u8 idx (exact); t = scale[n]*(c1*sa[m]*dot + c0*S0[m]).
// Dense: B = s8 hi/lo;       t = sa[m]*sw[n]*dot + bias[n].
// dot = acc0 + acc1/254.
template<int GHOST, int BIAS, int GELU, int RESID>
__global__ void __launch_bounds__(256, 1)
igemm(const char* __restrict__ Ah, const char* __restrict__ Al,
      const float* __restrict__ saA, const float* __restrict__ S0A,
      const void* __restrict__ Bhv, const char* __restrict__ Bl,
      const float* __restrict__ swB,
      const float* __restrict__ bias, const float* __restrict__ scale,
      const float* __restrict__ lutp, const float* __restrict__ resid,
      float* __restrict__ C, int M, int N, int K) {
    const char* Bh = (const char*)Bhv;
    extern __shared__ __align__(128) char sm[];
    uint32_t smb = smem_u32(sm);

    int tid = threadIdx.x, wid = tid >> 5, lane = tid & 31;
    int grp = lane >> 2, tg = lane & 3;
    int wm = (wid & 1) * 64;
    int wn = (wid >> 1) * 32;
    int bm = blockIdx.x * 128;
    int bn = blockIdx.y * 128;

    constexpr int STAGE_B = (GHOST ? 3 : 4) * PLANE_B;

    int acc[2][16][4];
    #pragma unroll
    for (int t2 = 0; t2 < 2; t2++)
        #pragma unroll
        for (int i = 0; i < 16; i++)
            #pragma unroll
            for (int e = 0; e < 4; e++) acc[t2][i][e] = 0;

    int nch = K / 64;

    auto issue = [&](int c) {
        uint32_t sb = smb + (uint32_t)(c % 3) * STAGE_B;
        int kb = c * 64;
        #pragma unroll
        for (int rep = 0; rep < 2; rep++) {
            int cid = tid + rep * 256;
            int row = cid >> 2, ch = cid & 3;
            uint32_t doff = (uint32_t)(row * ROW_B + ch * 16);
            size_t ga = (size_t)(bm + row) * K + kb + ch * 16;
            cp16(sb + doff,            Ah + ga);
            cp16(sb + PLANE_B + doff,  Al + ga);
            int br = bn + row; if (br >= N) br = N - 1;
            size_t gb = (size_t)br * K + kb + ch * 16;
            cp16(sb + 2 * PLANE_B + doff, Bh + gb);
            if (!GHOST) cp16(sb + 3 * PLANE_B + doff, Bl + gb);
        }
        CP_COMMIT();
    };

    issue(0);
    if (nch > 1) issue(1);

    uint32_t aoffL = (uint32_t)((wm + (lane & 15)) * ROW_B + ((lane >> 4) << 4));
    uint32_t boffL = (uint32_t)((wn + (lane & 7) + ((lane >> 4) << 3)) * ROW_B
                                + (((lane >> 3) & 1) << 4));

    for (int c = 0; c < nch; c++) {
        if (c + 1 < nch) CP_WAIT1(); else CP_WAIT0();
        __syncthreads();
        if (c + 2 < nch) issue(c + 2);

        uint32_t sb = smb + (uint32_t)(c % 3) * STAGE_B;
        #pragma unroll
        for (int ks = 0; ks < 2; ks++) {
            uint32_t ao = sb + aoffL + ks * 32;
            uint32_t bo = sb + 2 * PLANE_B + boffL + ks * 32;
            unsigned ah[4][4], al[4][4], bh[4][2], bl[4][2];
            #pragma unroll
            for (int i = 0; i < 4; i++) {
                LDSM4(ah[i][0], ah[i][1], ah[i][2], ah[i][3], ao + i * 16 * ROW_B);
                LDSM4(al[i][0], al[i][1], al[i][2], al[i][3], ao + PLANE_B + i * 16 * ROW_B);
            }
            #pragma unroll
            for (int j2 = 0; j2 < 2; j2++) {
                unsigned r0, r1, r2, r3;
                LDSM4(r0, r1, r2, r3, bo + j2 * 16 * ROW_B);
                bh[j2 * 2][0] = r0; bh[j2 * 2][1] = r1;
                bh[j2 * 2 + 1][0] = r2; bh[j2 * 2 + 1][1] = r3;
                if (!GHOST) {
                    LDSM4(r0, r1, r2, r3, bo + PLANE_B + j2 * 16 * ROW_B);
                    bl[j2 * 2][0] = r0; bl[j2 * 2][1] = r1;
                    bl[j2 * 2 + 1][0] = r2; bl[j2 * 2 + 1][1] = r3;
                }
            }
            #pragma unroll
            for (int i = 0; i < 4; i++)
                #pragma unroll
                for (int j = 0; j < 4; j++) {
                    if (GHOST) {
                        IMMA_SU(acc[0][i * 4 + j], ah[i][0], ah[i][1], ah[i][2], ah[i][3], bh[j][0], bh[j][1]);
                        IMMA_SU(acc[1][i * 4 + j], al[i][0], al[i][1], al[i][2], al[i][3], bh[j][0], bh[j][1]);
                    } else {
                        IMMA_SS(acc[0][i * 4 + j], ah[i][0], ah[i][1], ah[i][2], ah[i][3], bh[j][0], bh[j][1]);
                        IMMA_SS(acc[1][i * 4 + j], ah[i][0], ah[i][1], ah[i][2], ah[i][3], bl[j][0], bl[j][1]);
                        IMMA_SS(acc[1][i * 4 + j], al[i][0], al[i][1], al[i][2], al[i][3], bh[j][0], bh[j][1]);
                    }
                }
        }
        __syncthreads();
    }

    // ---- epilogue ----
    float c0f = 0.f, c1f = 0.f;
    if (GHOST) {
        float L0 = __ldg(lutp), L255 = __ldg(lutp + 255);
        c0f = L0;
        c1f = (L255 - L0) * (1.0f / 255.0f);
    }
    #pragma unroll
    for (int i = 0; i < 4; i++) {
        int mA = bm + wm + i * 16 + grp;
        float sa0 = saA[mA], sa1 = saA[mA + 8];
        float s00 = 0.f, s01 = 0.f;
        if (GHOST) { s00 = S0A[mA]; s01 = S0A[mA + 8]; }
        #pragma unroll
        for (int j = 0; j < 4; j++) {
            int n0 = bn + wn + j * 8 + 2 * tg;
            #pragma unroll
            for (int e = 0; e < 4; e++) {
                int m = mA + ((e >= 2) ? 8 : 0);
                int n = n0 + (e & 1);
                if (n < N) {
                    float dot = (float)acc[0][i * 4 + j][e]
                              + (float)acc[1][i * 4 + j][e] * (1.0f / 254.0f);
                    float sa_ = (e >= 2) ? sa1 : sa0;
                    float t;
                    if (GHOST) {
                        float s0_ = (e >= 2) ? s01 : s00;
                        t = (c1f * sa_ * dot + c0f * s0_) * scale[n];
                    } else {
                        t = sa_ * swB[n] * dot + bias[n];
                    }
                    if (GELU)  t = gelu_tanh(t);
                    if (RESID) t += resid[(size_t)m * N + n];
                    C[(size_t)m * N + n] = t;
                }
            }
        }
    }
}

// ---------------- launch ----------------
extern "C" void kernel_launch(void* const* d_in, const int* in_sizes, int n_in,
                              void* d_out, int out_size) {
    const float* lut        = (const float*)d_in[0];
    const float* tok_emb    = (const float*)d_in[1];
    const float* pos_emb    = (const float*)d_in[2];
    const float* ln1_g      = (const float*)d_in[3];
    const float* ln1_b      = (const float*)d_in[4];
    const float* in_w       = (const float*)d_in[5];
    const float* in_b       = (const float*)d_in[6];
    const float* out_w      = (const float*)d_in[7];
    const float* out_b      = (const float*)d_in[8];
    const float* ln2_g      = (const float*)d_in[9];
    const float* ln2_b      = (const float*)d_in[10];
    const float* mlp1_scale = (const float*)d_in[11];
    const float* mlp2_scale = (const float*)d_in[12];
    const float* lnf_g      = (const float*)d_in[13];
    const float* lnf_b      = (const float*)d_in[14];
    const float* head_scale = (const float*)d_in[15];
    const int*   mlp1_idx   = (const int*)d_in[16];
    const int*   mlp2_idx   = (const int*)d_in[17];
    const int*   head_idx   = (const int*)d_in[18];
    const int*   idx        = (const int*)d_in[19];
    float* out = (float*)d_out;

    float *x, *qkv, *att, *mlp, *sa, *s0;
    char *qa_h, *qa_l;
    char *pwq_h, *pwq_l, *pwp_h, *pwp_l;
    float *pwq_s, *pwp_s;
    unsigned char *pw1, *pw2, *pwh;
    cudaGetSymbolAddress((void**)&x,     g_x);
    cudaGetSymbolAddress((void**)&qkv,   g_qkv);
    cudaGetSymbolAddress((void**)&att,   g_att);
    cudaGetSymbolAddress((void**)&mlp,   g_mlp);
    cudaGetSymbolAddress((void**)&sa,    g_sa);
    cudaGetSymbolAddress((void**)&s0,    g_s0);
    cudaGetSymbolAddress((void**)&qa_h,  g_qa_h);
    cudaGetSymbolAddress((void**)&qa_l,  g_qa_l);
    cudaGetSymbolAddress((void**)&pwq_h, wq_h);
    cudaGetSymbolAddress((void**)&pwq_l, wq_l);
    cudaGetSymbolAddress((void**)&pwq_s, wq_s);
    cudaGetSymbolAddress((void**)&pwp_h, wp_h);
    cudaGetSymbolAddress((void**)&pwp_l, wp_l);
    cudaGetSymbolAddress((void**)&pwp_s, wp_s);
    cudaGetSymbolAddress((void**)&pw1,   w1_u);
    cudaGetSymbolAddress((void**)&pw2,   w2_u);
    cudaGetSymbolAddress((void**)&pwh,   wh_u);

    static int attr_done = 0;
    if (!attr_done) {
        cudaFuncSetAttribute(igemm<0,1,0,0>, cudaFuncAttributeMaxDynamicSharedMemorySize, SM_DENSE);
        cudaFuncSetAttribute(igemm<0,1,0,1>, cudaFuncAttributeMaxDynamicSharedMemorySize, SM_DENSE);
        cudaFuncSetAttribute(igemm<1,0,1,0>, cudaFuncAttributeMaxDynamicSharedMemorySize, SM_GHOST);
        cudaFuncSetAttribute(igemm<1,0,0,1>, cudaFuncAttributeMaxDynamicSharedMemorySize, SM_GHOST);
        cudaFuncSetAttribute(igemm<1,0,0,0>, cudaFuncAttributeMaxDynamicSharedMemorySize, SM_GHOST);
        attr_done = 1;
    }

    // ---- pre-conversion ----
    conv_w_int8<<<NL * QKVW, 256>>>(in_w,  pwq_h, pwq_l, pwq_s, DIMN);
    conv_w_int8<<<NL * DIMN, 256>>>(out_w, pwp_h, pwp_l, pwp_s, DIMN);
    {
        size_t n;
        n = (size_t)NL * HID * DIMN;
        conv_idx_u8<<<(unsigned)((n / 16 + 255) / 256), 256>>>(mlp1_idx, pw1, n);
        n = (size_t)NL * DIMN * HID;
        conv_idx_u8<<<(unsigned)((n / 16 + 255) / 256), 256>>>(mlp2_idx, pw2, n);
        n = (size_t)VOCAB * DIMN;
        conv_idx_u8<<<(unsigned)((n / 16 + 255) / 256), 256>>>(head_idx, pwh, n);
    }

    embed_kernel<<<BT, 256>>>(idx, tok_emb, pos_emb, x);

    for (int l = 0; l < NL; l++) {
        ln_quant<<<BT, 256>>>(x, ln1_g + l * DIMN, ln1_b + l * DIMN, qa_h, qa_l, sa, s0);
        {
            dim3 grid(BT / 128, QKVW / 128);   // 16 x 18
            igemm<0,1,0,0><<<grid, 256, SM_DENSE>>>(
                qa_h, qa_l, sa, s0,
                pwq_h + (size_t)l * QKVW * DIMN, pwq_l + (size_t)l * QKVW * DIMN,
                pwq_s + (size_t)l * QKVW,
                in_b + (size_t)l * QKVW, nullptr, nullptr, nullptr,
                qkv, BT, QKVW, DIMN);
        }
        {
            dim3 grid(SEQ, NH, BATCH);
            attn_kernel<<<grid, 128>>>(qkv, att);
        }
        quant_rows<<<BT, 256>>>(att, qa_h, qa_l, sa, s0, DIMN);
        {
            dim3 grid(BT / 128, DIMN / 128);   // 16 x 6
            igemm<0,1,0,1><<<grid, 256, SM_DENSE>>>(
                qa_h, qa_l, sa, s0,
                pwp_h + (size_t)l * DIMN * DIMN, pwp_l + (size_t)l * DIMN * DIMN,
                pwp_s + (size_t)l * DIMN,
                out_b + (size_t)l * DIMN, nullptr, nullptr, x,
                x, BT, DIMN, DIMN);
        }
        ln_quant<<<BT, 256>>>(x, ln2_g + l * DIMN, ln2_b + l * DIMN, qa_h, qa_l, sa, s0);
        {
            dim3 grid(BT / 128, HID / 128);    // 16 x 24
            igemm<1,0,1,0><<<grid, 256, SM_GHOST>>>(
                qa_h, qa_l, sa, s0,
                pw1 + (size_t)l * HID * DIMN, nullptr, nullptr,
                nullptr, mlp1_scale + (size_t)l * HID, lut, nullptr,
                mlp, BT, HID, DIMN);
        }
        quant_rows<<<BT, 256>>>(mlp, qa_h, qa_l, sa, s0, HID);
        {
            dim3 grid(BT / 128, DIMN / 128);   // 16 x 6
            igemm<1,0,0,1><<<grid, 256, SM_GHOST>>>(
                qa_h, qa_l, sa, s0,
                pw2 + (size_t)l * DIMN * HID, nullptr, nullptr,
                nullptr, mlp2_scale + (size_t)l * DIMN, lut, x,
                x, BT, DIMN, HID);
        }
    }

    ln_quant<<<BT, 256>>>(x, lnf_g, lnf_b, qa_h, qa_l, sa, s0);

    {
        dim3 grid(BT / 128, (VOCAB + 127) / 128);   // 16 x 393
        igemm<1,0,0,0><<<grid, 256, SM_GHOST>>>(
            qa_h, qa_l, sa, s0,
            pwh, nullptr, nullptr,
            nullptr, head_scale, lut, nullptr,
            out, BT, VOCAB, DIMN);
    }
}

// round 8
// speedup vs baseline: 1.3132x; 1.3132x over previous
#include <cuda_runtime.h>
#include <cuda_fp16.h>
#include <cstdint>
#include <math.h>

// ---------------- problem constants ----------------
#define DIMN 768
#define NL   13
#define NH   12
#define HD   64
#define VOCAB 50257
#define SEQ  512
#define BATCH 4
#define HID  3072
#define BT   (BATCH*SEQ)      // 2048
#define QKVW (3*DIMN)         // 2304

// ---------------- gemm config ----------------
// Tile 128x128, BK=32 halves. 8 warps (2m x 4n), warp tile 64x32.
// SMEM plane: 128 rows x 80 bytes (64B data + 16 pad). 3 stages.
#define PLANE_B 10240
#define ROW_B   80
#define SM_GHOST (3 * 2 * PLANE_B)   // 61440  -> 2 CTAs/SM
#define SM_DENSE (3 * 4 * PLANE_B)   // 122880 -> 1 CTA/SM

// ---------------- scratch (device globals; no allocation) ----------------
__device__ float  g_x   [(size_t)BT*DIMN];
__device__ float  g_qkv [(size_t)BT*QKVW];
__device__ float  g_s0_ln [BT];
__device__ float  g_s0_mlp[BT];
__device__ __half g_ln_hi [(size_t)BT*DIMN];
__device__ __half g_ln_lo [(size_t)BT*DIMN];
__device__ __half g_att_hi[(size_t)BT*DIMN];
__device__ __half g_att_lo[(size_t)BT*DIMN];
__device__ __half g_mlp_hi[(size_t)BT*HID];
__device__ __half g_mlp_lo[(size_t)BT*HID];
// pre-converted weight planes
__device__ __half w_qkv_hi [(size_t)NL*QKVW*DIMN];
__device__ __half w_qkv_lo [(size_t)NL*QKVW*DIMN];
__device__ __half w_proj_hi[(size_t)NL*DIMN*DIMN];
__device__ __half w_proj_lo[(size_t)NL*DIMN*DIMN];
__device__ __half w_mlp1_i [(size_t)NL*HID*DIMN];   // idx as fp16 (exact)
__device__ __half w_mlp2_i [(size_t)NL*DIMN*HID];
__device__ __half w_head_i [(size_t)VOCAB*DIMN];

// ---------------- helpers ----------------
__device__ __forceinline__ void split1(float v, __half& h, __half& l) {
    h = __float2half_rn(v);
    l = __float2half_rn(v - __half2float(h));
}
__device__ __forceinline__ float gelu_tanh(float x) {
    float x3 = x * x * x;
    return 0.5f * x * (1.0f + tanhf(0.7978845608028654f * (x + 0.044715f * x3)));
}
__device__ __forceinline__ uint32_t smem_u32(const void* p) {
    uint32_t a;
    asm("{ .reg .u64 t; cvta.to.shared.u64 t, %1; cvt.u32.u64 %0, t; }" : "=r"(a) : "l"(p));
    return a;
}
__device__ __forceinline__ void cp16(uint32_t dst, const void* src) {
    asm volatile("cp.async.cg.shared.global [%0], [%1], 16;" :: "r"(dst), "l"(src));
}
#define CP_COMMIT() asm volatile("cp.async.commit_group;" ::: "memory")
#define CP_WAIT1()  asm volatile("cp.async.wait_group 1;" ::: "memory")
#define CP_WAIT0()  asm volatile("cp.async.wait_group 0;" ::: "memory")

#define LDSM4(r0, r1, r2, r3, addr)                                           \
    asm volatile("ldmatrix.sync.aligned.m8n8.x4.shared.b16 {%0,%1,%2,%3}, [%4];" \
        : "=r"(r0), "=r"(r1), "=r"(r2), "=r"(r3) : "r"(addr))

#define MMA16816(c, a0, a1, a2, a3, b0, b1)                                   \
    asm volatile(                                                             \
        "mma.sync.aligned.m16n8k16.row.col.f32.f16.f16.f32 "                  \
        "{%0,%1,%2,%3}, {%4,%5,%6,%7}, {%8,%9}, {%0,%1,%2,%3};"               \
        : "+f"((c)[0]), "+f"((c)[1]), "+f"((c)[2]), "+f"((c)[3])              \
        : "r"(a0), "r"(a1), "r"(a2), "r"(a3), "r"(b0), "r"(b1))

// ---------------- conversion pre-passes ----------------
__global__ void conv_w_f32(const float* __restrict__ w, __half* __restrict__ hi,
                           __half* __restrict__ lo, size_t n) {
    size_t i = ((size_t)blockIdx.x * blockDim.x + threadIdx.x) * 4;
    if (i >= n) return;
    float4 v = *(const float4*)(w + i);
    __half h[4], l[4];
    split1(v.x, h[0], l[0]); split1(v.y, h[1], l[1]);
    split1(v.z, h[2], l[2]); split1(v.w, h[3], l[3]);
    *(ushort4*)(hi + i) = make_ushort4(__half_as_ushort(h[0]), __half_as_ushort(h[1]),
                                       __half_as_ushort(h[2]), __half_as_ushort(h[3]));
    *(ushort4*)(lo + i) = make_ushort4(__half_as_ushort(l[0]), __half_as_ushort(l[1]),
                                       __half_as_ushort(l[2]), __half_as_ushort(l[3]));
}

__global__ void conv_idx(const int* __restrict__ idx, __half* __restrict__ o, size_t n) {
    size_t i = ((size_t)blockIdx.x * blockDim.x + threadIdx.x) * 8;
    if (i >= n) return;
    int4 a = *(const int4*)(idx + i);
    int4 b = *(const int4*)(idx + i + 4);
    int id[8] = {a.x, a.y, a.z, a.w, b.x, b.y, b.z, b.w};
    ushort h[8];
    #pragma unroll
    for (int j = 0; j < 8; j++)
        h[j] = __half_as_ushort(__float2half_rn((float)id[j]));   // exact, idx<=255
    *(uint4*)(o + i) = *(uint4*)h;
}

// ---------------- embedding ----------------
__global__ void embed_kernel(const int* __restrict__ idx, const float* __restrict__ tok,
                             const float* __restrict__ pos, float* __restrict__ x) {
    int r = blockIdx.x;
    int t = r % SEQ;
    int token = idx[r];
    const float* tr = tok + (size_t)token * DIMN;
    const float* pr = pos + (size_t)t * DIMN;
    float* xr = x + (size_t)r * DIMN;
    for (int d = threadIdx.x; d < DIMN; d += blockDim.x)
        xr[d] = tr[d] + pr[d];
}

// ---------------- layernorm -> split planes + rowsum ----------------
__global__ void ln_kernel(const float* __restrict__ x, const float* __restrict__ g,
                          const float* __restrict__ b,
                          __half* __restrict__ ohi, __half* __restrict__ olo,
                          float* __restrict__ s0) {
    int r = blockIdx.x;
    int tid = threadIdx.x;
    const float* xr = x + (size_t)r * DIMN;
    __shared__ float red[256];

    float v0 = xr[tid], v1 = xr[tid + 256], v2 = xr[tid + 512];
    red[tid] = v0 + v1 + v2;
    __syncthreads();
    for (int s = 128; s > 0; s >>= 1) { if (tid < s) red[tid] += red[tid + s]; __syncthreads(); }
    float mean = red[0] * (1.0f / DIMN);
    __syncthreads();
    float d0 = v0 - mean, d1 = v1 - mean, d2 = v2 - mean;
    red[tid] = d0 * d0 + d1 * d1 + d2 * d2;
    __syncthreads();
    for (int s = 128; s > 0; s >>= 1) { if (tid < s) red[tid] += red[tid + s]; __syncthreads(); }
    float inv = rsqrtf(red[0] * (1.0f / DIMN) + 1e-5f);
    float o0 = d0 * inv * g[tid]       + b[tid];
    float o1 = d1 * inv * g[tid + 256] + b[tid + 256];
    float o2 = d2 * inv * g[tid + 512] + b[tid + 512];
    __syncthreads();
    red[tid] = o0 + o1 + o2;
    __syncthreads();
    for (int s = 128; s > 0; s >>= 1) { if (tid < s) red[tid] += red[tid + s]; __syncthreads(); }
    if (tid == 0) s0[r] = red[0];
    __half h, l;
    size_t base = (size_t)r * DIMN;
    split1(o0, h, l); ohi[base + tid]       = h; olo[base + tid]       = l;
    split1(o1, h, l); ohi[base + tid + 256] = h; olo[base + tid + 256] = l;
    split1(o2, h, l); ohi[base + tid + 512] = h; olo[base + tid + 512] = l;
}

// ---------------- rowsum of split planes ----------------
__global__ void rowsum_kernel(const __half* __restrict__ hi, const __half* __restrict__ lo,
                              float* __restrict__ s0, int K) {
    int r = blockIdx.x;
    int tid = threadIdx.x;
    __shared__ float red[256];
    float s = 0.f;
    for (int k = tid; k < K; k += 256)
        s += __half2float(hi[(size_t)r * K + k]) + __half2float(lo[(size_t)r * K + k]);
    red[tid] = s;
    __syncthreads();
    for (int st = 128; st > 0; st >>= 1) { if (tid < st) red[tid] += red[tid + st]; __syncthreads(); }
    if (tid == 0) s0[r] = red[0];
}

// ---------------- attention -> split planes ----------------
__global__ void attn_kernel(const float* __restrict__ qkv,
                            __half* __restrict__ ohi, __half* __restrict__ olo) {
    int q = blockIdx.x, h = blockIdx.y, b = blockIdx.z;
    int tid = threadIdx.x;
    __shared__ float qs[HD];
    __shared__ float sc[SEQ];
    __shared__ float red[128];

    const float* qrow = qkv + ((size_t)(b * SEQ + q)) * QKVW + h * HD;
    if (tid < HD) qs[tid] = qrow[tid];
    __syncthreads();

    int n = q + 1;
    for (int k = tid; k < n; k += 128) {
        const float* krow = qkv + ((size_t)(b * SEQ + k)) * QKVW + DIMN + h * HD;
        float s = 0.f;
        #pragma unroll
        for (int d = 0; d < HD; d++) s += qs[d] * krow[d];
        sc[k] = s * 0.125f;
    }
    __syncthreads();

    float m = -1e30f;
    for (int k = tid; k < n; k += 128) m = fmaxf(m, sc[k]);
    red[tid] = m; __syncthreads();
    for (int s = 64; s > 0; s >>= 1) { if (tid < s) red[tid] = fmaxf(red[tid], red[tid + s]); __syncthreads(); }
    m = red[0];
    __syncthreads();

    float ssum = 0.f;
    for (int k = tid; k < n; k += 128) { float e = expf(sc[k] - m); sc[k] = e; ssum += e; }
    red[tid] = ssum; __syncthreads();
    for (int s = 64; s > 0; s >>= 1) { if (tid < s) red[tid] += red[tid + s]; __syncthreads(); }
    float inv = 1.0f / red[0];
    __syncthreads();

    int d = tid & 63, half_ = tid >> 6;
    float acc = 0.f;
    for (int k = half_; k < n; k += 2) {
        const float* vrow = qkv + ((size_t)(b * SEQ + k)) * QKVW + 2 * DIMN + h * HD;
        acc += sc[k] * vrow[d];
    }
    red[tid] = acc; __syncthreads();
    if (tid < HD) {
        float val = (red[tid] + red[tid + 64]) * inv;
        __half hh, ll; split1(val, hh, ll);
        size_t off = ((size_t)(b * SEQ + q)) * DIMN + h * HD + tid;
        ohi[off] = hh; olo[off] = ll;
    }
}

// ---------------- HMMA GEMM ----------------
// C[M,N] = A[M,K] @ B[N,K]^T, fp16 operands.
// GHOST: single-term (A_hi x idx); epilogue t = scale[n]*(c1*acc + c0*S0[m]).
//        SMEM planes per stage: A@0, B@1 (2 planes) -> 2 CTAs/SM.
// Dense: 3-term hi/lo split; planes A_hi, A_lo, B_hi, B_lo (4 planes).
template<int GHOST, int BIAS, int GELU, int RESID, int OUTSPLIT>
__global__ void __launch_bounds__(256, GHOST ? 2 : 1)
hgemm(const __half* __restrict__ Ahi, const __half* __restrict__ Alo,
      const __half* __restrict__ Bhi, const __half* __restrict__ Blo,
      const float* __restrict__ bias, const float* __restrict__ scale,
      const float* __restrict__ S0, const float* __restrict__ lutp,
      const float* __restrict__ resid,
      float* __restrict__ C, __half* __restrict__ Ohi, __half* __restrict__ Olo,
      int M, int N, int K) {
    constexpr int PLANES = GHOST ? 2 : 4;
    constexpr int BPL = GHOST ? 1 : 2;        // index of B plane
    constexpr int STAGE_B = PLANES * PLANE_B;

    extern __shared__ __align__(128) char sm[];
    uint32_t smb = smem_u32(sm);

    int tid = threadIdx.x, wid = tid >> 5, lane = tid & 31;
    int grp = lane >> 2, tg = lane & 3;
    int wm = (wid & 1) * 64;
    int wn = (wid >> 1) * 32;
    int bm = blockIdx.x * 128;
    int bn = blockIdx.y * 128;

    float acc[16][4];
    #pragma unroll
    for (int i = 0; i < 16; i++)
        #pragma unroll
        for (int e = 0; e < 4; e++) acc[i][e] = 0.f;

    int nch = K / 32;

    // loader mapping: ids tid, tid+256 -> (row, 16B chunk)
    int row0 = tid >> 2,          ch0 = (tid & 3);
    int row1 = (tid + 256) >> 2,  ch1 = ch0;
    int br0 = bn + row0; if (br0 >= N) br0 = N - 1;
    int br1 = bn + row1; if (br1 >= N) br1 = N - 1;

    auto issue = [&](int c) {
        uint32_t sb = smb + (uint32_t)(c % 3) * STAGE_B;
        int kb = c * 32;
        {
            uint32_t doff = (uint32_t)(row0 * ROW_B + ch0 * 16);
            size_t go = (size_t)(bm + row0) * K + kb + ch0 * 8;
            cp16(sb + doff, Ahi + go);
            if (!GHOST) cp16(sb + PLANE_B + doff, Alo + go);
            size_t gb = (size_t)br0 * K + kb + ch0 * 8;
            cp16(sb + BPL * PLANE_B + doff, Bhi + gb);
            if (!GHOST) cp16(sb + 3 * PLANE_B + doff, Blo + gb);
        }
        {
            uint32_t doff = (uint32_t)(row1 * ROW_B + ch1 * 16);
            size_t go = (size_t)(bm + row1) * K + kb + ch1 * 8;
            cp16(sb + doff, Ahi + go);
            if (!GHOST) cp16(sb + PLANE_B + doff, Alo + go);
            size_t gb = (size_t)br1 * K + kb + ch1 * 8;
            cp16(sb + BPL * PLANE_B + doff, Bhi + gb);
            if (!GHOST) cp16(sb + 3 * PLANE_B + doff, Blo + gb);
        }
        CP_COMMIT();
    };

    issue(0);
    if (nch > 1) issue(1);

    // ldmatrix lane offsets
    uint32_t aoffL = (uint32_t)((wm + (lane & 15)) * ROW_B + ((lane >> 4) << 4));
    uint32_t boffL = (uint32_t)((wn + (lane & 7) + ((lane >> 4) << 3)) * ROW_B
                                + (((lane >> 3) & 1) << 4));

    for (int c = 0; c < nch; c++) {
        if (c + 1 < nch) CP_WAIT1(); else CP_WAIT0();
        __syncthreads();
        if (c + 2 < nch) issue(c + 2);

        uint32_t sb = smb + (uint32_t)(c % 3) * STAGE_B;
        #pragma unroll
        for (int ks = 0; ks < 2; ks++) {
            uint32_t ao = sb + aoffL + ks * 32;
            uint32_t bo = sb + BPL * PLANE_B + boffL + ks * 32;
            unsigned ah[4][4], al[4][4], bh[4][2], bl[4][2];
            #pragma unroll
            for (int i = 0; i < 4; i++) {
                LDSM4(ah[i][0], ah[i][1], ah[i][2], ah[i][3], ao + i * 16 * ROW_B);
                if (!GHOST)
                    LDSM4(al[i][0], al[i][1], al[i][2], al[i][3], ao + PLANE_B + i * 16 * ROW_B);
            }
            #pragma unroll
            for (int j2 = 0; j2 < 2; j2++) {
                unsigned r0, r1, r2, r3;
                LDSM4(r0, r1, r2, r3, bo + j2 * 16 * ROW_B);
                bh[j2 * 2][0] = r0; bh[j2 * 2][1] = r1;
                bh[j2 * 2 + 1][0] = r2; bh[j2 * 2 + 1][1] = r3;
                if (!GHOST) {
                    LDSM4(r0, r1, r2, r3, bo + PLANE_B + j2 * 16 * ROW_B);
                    bl[j2 * 2][0] = r0; bl[j2 * 2][1] = r1;
                    bl[j2 * 2 + 1][0] = r2; bl[j2 * 2 + 1][1] = r3;
                }
            }
            #pragma unroll
            for (int i = 0; i < 4; i++)
                #pragma unroll
                for (int j = 0; j < 4; j++) {
                    float* a4 = acc[i * 4 + j];
                    MMA16816(a4, ah[i][0], ah[i][1], ah[i][2], ah[i][3], bh[j][0], bh[j][1]);
                    if (!GHOST) {
                        MMA16816(a4, al[i][0], al[i][1], al[i][2], al[i][3], bh[j][0], bh[j][1]);
                        MMA16816(a4, ah[i][0], ah[i][1], ah[i][2], ah[i][3], bl[j][0], bl[j][1]);
                    }
                }
        }
        __syncthreads();
    }

    // ---- epilogue ----
    float c0f = 0.f, c1f = 0.f;
    if (GHOST) {
        float L0 = __ldg(lutp), L255 = __ldg(lutp + 255);
        c0f = L0;
        c1f = (L255 - L0) * (1.0f / 255.0f);
    }
    #pragma unroll
    for (int i = 0; i < 4; i++) {
        int mA = bm + wm + i * 16 + grp;
        float s0a = 0.f, s0b = 0.f;
        if (GHOST) { s0a = S0[mA]; s0b = S0[mA + 8]; }
        #pragma unroll
        for (int j = 0; j < 4; j++) {
            int n0 = bn + wn + j * 8 + 2 * tg;
            #pragma unroll
            for (int e = 0; e < 4; e++) {
                int m = mA + ((e >= 2) ? 8 : 0);
                int n = n0 + (e & 1);
                if (n < N) {
                    float t = acc[i * 4 + j][e];
                    if (GHOST) t = (c1f * t + c0f * ((e >= 2) ? s0b : s0a)) * scale[n];
                    if (BIAS)  t += bias[n];
                    if (GELU)  t = gelu_tanh(t);
                    if (RESID) t += resid[(size_t)m * N + n];
                    if (OUTSPLIT) {
                        __half hh, ll; split1(t, hh, ll);
                        Ohi[(size_t)m * N + n] = hh;
                        Olo[(size_t)m * N + n] = ll;
                    } else {
                        C[(size_t)m * N + n] = t;
                    }
                }
            }
        }
    }
}

// ---------------- launch ----------------
extern "C" void kernel_launch(void* const* d_in, const int* in_sizes, int n_in,
                              void* d_out, int out_size) {
    const float* lut        = (const float*)d_in[0];
    const float* tok_emb    = (const float*)d_in[1];
    const float* pos_emb    = (const float*)d_in[2];
    const float* ln1_g      = (const float*)d_in[3];
    const float* ln1_b      = (const float*)d_in[4];
    const float* in_w       = (const float*)d_in[5];
    const float* in_b       = (const float*)d_in[6];
    const float* out_w      = (const float*)d_in[7];
    const float* out_b      = (const float*)d_in[8];
    const float* ln2_g      = (const float*)d_in[9];
    const float* ln2_b      = (const float*)d_in[10];
    const float* mlp1_scale = (const float*)d_in[11];
    const float* mlp2_scale = (const float*)d_in[12];
    const float* lnf_g      = (const float*)d_in[13];
    const float* lnf_b      = (const float*)d_in[14];
    const float* head_scale = (const float*)d_in[15];
    const int*   mlp1_idx   = (const int*)d_in[16];
    const int*   mlp2_idx   = (const int*)d_in[17];
    const int*   head_idx   = (const int*)d_in[18];
    const int*   idx        = (const int*)d_in[19];
    float* out = (float*)d_out;

    float *x, *qkv, *s0_ln, *s0_mlp;
    __half *ln_hi, *ln_lo, *att_hi, *att_lo, *mlp_hi, *mlp_lo;
    __half *wq_hi, *wq_lo, *wp_hi, *wp_lo, *w1_i, *w2_i, *wh_i;
    cudaGetSymbolAddress((void**)&x,      g_x);
    cudaGetSymbolAddress((void**)&qkv,    g_qkv);
    cudaGetSymbolAddress((void**)&s0_ln,  g_s0_ln);
    cudaGetSymbolAddress((void**)&s0_mlp, g_s0_mlp);
    cudaGetSymbolAddress((void**)&ln_hi,  g_ln_hi);
    cudaGetSymbolAddress((void**)&ln_lo,  g_ln_lo);
    cudaGetSymbolAddress((void**)&att_hi, g_att_hi);
    cudaGetSymbolAddress((void**)&att_lo, g_att_lo);
    cudaGetSymbolAddress((void**)&mlp_hi, g_mlp_hi);
    cudaGetSymbolAddress((void**)&mlp_lo, g_mlp_lo);
    cudaGetSymbolAddress((void**)&wq_hi,  w_qkv_hi);
    cudaGetSymbolAddress((void**)&wq_lo,  w_qkv_lo);
    cudaGetSymbolAddress((void**)&wp_hi,  w_proj_hi);
    cudaGetSymbolAddress((void**)&wp_lo,  w_proj_lo);
    cudaGetSymbolAddress((void**)&w1_i,   w_mlp1_i);
    cudaGetSymbolAddress((void**)&w2_i,   w_mlp2_i);
    cudaGetSymbolAddress((void**)&wh_i,   w_head_i);

    static int attr_done = 0;
    if (!attr_done) {
        cudaFuncSetAttribute(hgemm<0,1,0,0,0>, cudaFuncAttributeMaxDynamicSharedMemorySize, SM_DENSE);
        cudaFuncSetAttribute(hgemm<0,1,0,1,0>, cudaFuncAttributeMaxDynamicSharedMemorySize, SM_DENSE);
        cudaFuncSetAttribute(hgemm<1,0,1,0,1>, cudaFuncAttributeMaxDynamicSharedMemorySize, SM_GHOST);
        cudaFuncSetAttribute(hgemm<1,0,0,1,0>, cudaFuncAttributeMaxDynamicSharedMemorySize, SM_GHOST);
        cudaFuncSetAttribute(hgemm<1,0,0,0,0>, cudaFuncAttributeMaxDynamicSharedMemorySize, SM_GHOST);
        attr_done = 1;
    }

    // ---- pre-conversion (each forward; deterministic) ----
    {
        size_t n;
        n = (size_t)NL*QKVW*DIMN;
        conv_w_f32<<<(unsigned)((n/4 + 255)/256), 256>>>(in_w,  wq_hi, wq_lo, n);
        n = (size_t)NL*DIMN*DIMN;
        conv_w_f32<<<(unsigned)((n/4 + 255)/256), 256>>>(out_w, wp_hi, wp_lo, n);
        n = (size_t)NL*HID*DIMN;
        conv_idx<<<(unsigned)((n/8 + 255)/256), 256>>>(mlp1_idx, w1_i, n);
        n = (size_t)NL*DIMN*HID;
        conv_idx<<<(unsigned)((n/8 + 255)/256), 256>>>(mlp2_idx, w2_i, n);
        n = (size_t)VOCAB*DIMN;
        conv_idx<<<(unsigned)((n/8 + 255)/256), 256>>>(head_idx, wh_i, n);
    }

    embed_kernel<<<BT, 256>>>(idx, tok_emb, pos_emb, x);

    for (int l = 0; l < NL; l++) {
        ln_kernel<<<BT, 256>>>(x, ln1_g + l * DIMN, ln1_b + l * DIMN, ln_hi, ln_lo, s0_ln);
        {
            dim3 grid(BT / 128, QKVW / 128);   // 16 x 18
            hgemm<0,1,0,0,0><<<grid, 256, SM_DENSE>>>(
                ln_hi, ln_lo,
                wq_hi + (size_t)l * QKVW * DIMN, wq_lo + (size_t)l * QKVW * DIMN,
                in_b + (size_t)l * QKVW, nullptr, nullptr, nullptr, nullptr,
                qkv, nullptr, nullptr, BT, QKVW, DIMN);
        }
        {
            dim3 grid(SEQ, NH, BATCH);
            attn_kernel<<<grid, 128>>>(qkv, att_hi, att_lo);
        }
        {
            dim3 grid(BT / 128, DIMN / 128);   // 16 x 6
            hgemm<0,1,0,1,0><<<grid, 256, SM_DENSE>>>(
                att_hi, att_lo,
                wp_hi + (size_t)l * DIMN * DIMN, wp_lo + (size_t)l * DIMN * DIMN,
                out_b + (size_t)l * DIMN, nullptr, nullptr, nullptr, x,
                x, nullptr, nullptr, BT, DIMN, DIMN);
        }
        ln_kernel<<<BT, 256>>>(x, ln2_g + l * DIMN, ln2_b + l * DIMN, ln_hi, ln_lo, s0_ln);
        {
            dim3 grid(BT / 128, HID / 128);    // 16 x 24
            hgemm<1,0,1,0,1><<<grid, 256, SM_GHOST>>>(
                ln_hi, nullptr,
                w1_i + (size_t)l * HID * DIMN, nullptr,
                nullptr, mlp1_scale + (size_t)l * HID, s0_ln, lut, nullptr,
                nullptr, mlp_hi, mlp_lo, BT, HID, DIMN);
        }
        rowsum_kernel<<<BT, 256>>>(mlp_hi, mlp_lo, s0_mlp, HID);
        {
            dim3 grid(BT / 128, DIMN / 128);   // 16 x 6
            hgemm<1,0,0,1,0><<<grid, 256, SM_GHOST>>>(
                mlp_hi, nullptr,
                w2_i + (size_t)l * DIMN * HID, nullptr,
                nullptr, mlp2_scale + (size_t)l * DIMN, s0_mlp, lut, x,
                x, nullptr, nullptr, BT, DIMN, HID);
        }
    }

    ln_kernel<<<BT, 256>>>(x, lnf_g, lnf_b, ln_hi, ln_lo, s0_ln);

    {
        dim3 grid(BT / 128, (VOCAB + 127) / 128);   // 16 x 393
        hgemm<1,0,0,0,0><<<grid, 256, SM_GHOST>>>(
            ln_hi, nullptr, wh_i, nullptr,
            nullptr, head_scale, s0_ln, lut, nullptr,
            out, nullptr, nullptr, BT, VOCAB, DIMN);
    }
}